// round 4
// baseline (speedup 1.0000x reference)
#include <cuda_runtime.h>
#include <cuda_bf16.h>
#include <cstdint>
#include <math.h>

#define B_   8192
#define N_   4096
#define H_   256
#define NM_  2048
#define NLAY_ 8

typedef __nv_bfloat16 bf16;

// ---------------------------------------------------------------------------
// Device scratch (static globals — no allocation)
// ---------------------------------------------------------------------------
__device__ __align__(256) bf16 g_A_hi[(size_t)B_ * NM_];
__device__ __align__(256) bf16 g_A_lo[(size_t)B_ * NM_];
__device__ __align__(256) bf16 g_h1_hi[(size_t)B_ * H_];
__device__ __align__(256) bf16 g_h1_lo[(size_t)B_ * H_];
__device__ __align__(256) bf16 g_h2_hi[(size_t)B_ * H_];
__device__ __align__(256) bf16 g_h2_lo[(size_t)B_ * H_];
__device__ __align__(256) bf16 g_W1T_hi[(size_t)NLAY_ * H_ * NM_];
__device__ __align__(256) bf16 g_W1T_lo[(size_t)NLAY_ * H_ * NM_];
__device__ __align__(256) bf16 g_W2T_hi[(size_t)NLAY_ * H_ * H_];
__device__ __align__(256) bf16 g_W2T_lo[(size_t)NLAY_ * H_ * H_];
__device__ __align__(256) bf16 g_W3T_hi[(size_t)NLAY_ * N_ * H_];
__device__ __align__(256) bf16 g_W3T_lo[(size_t)NLAY_ * N_ * H_];

// ---------------------------------------------------------------------------
// Helpers
// ---------------------------------------------------------------------------
__device__ __forceinline__ uint32_t smem_u32(const void* p) {
    uint32_t a;
    asm("{ .reg .u64 t; cvta.to.shared.u64 t, %1; cvt.u32.u64 %0, t; }" : "=r"(a) : "l"(p));
    return a;
}

#define CPA16(sm, gp) \
    asm volatile("cp.async.cg.shared.global [%0], [%1], 16;" :: "r"(sm), "l"(gp) : "memory")
#define CP_COMMIT() asm volatile("cp.async.commit_group;" ::: "memory")
#define CP_WAIT1()  asm volatile("cp.async.wait_group 1;" ::: "memory")
#define CP_WAIT0()  asm volatile("cp.async.wait_group 0;" ::: "memory")

__device__ __forceinline__ void mma_bf16(float* c, const uint32_t* a, const uint32_t* b) {
    asm volatile(
        "mma.sync.aligned.m16n8k16.row.col.f32.bf16.bf16.f32 "
        "{%0,%1,%2,%3}, {%4,%5,%6,%7}, {%8,%9}, {%0,%1,%2,%3};"
        : "+f"(c[0]), "+f"(c[1]), "+f"(c[2]), "+f"(c[3])
        : "r"(a[0]), "r"(a[1]), "r"(a[2]), "r"(a[3]), "r"(b[0]), "r"(b[1]));
}

__device__ __forceinline__ int gather_im(int c, int p) {
    int g = c >> 5, m = c & 31;
    return g * 64 + 2 * m + ((p + g) & 1);
}
__device__ __forceinline__ int gather_iu(int c, int p) {
    int g = c >> 5, m = c & 31;
    return g * 64 + 2 * m + ((p + g + 1) & 1);
}

// ---------------------------------------------------------------------------
// SMEM layout: 2 stages, each stage holds 4 tiles of 128 x 32 bf16 with
// row stride 40 elements (80 bytes): Ahi | Alo | Bhi | Blo.
// 80B row stride => fragment lds (8 rows x 4 offsets) hits all 32 banks.
// ---------------------------------------------------------------------------
#define RS          40                 // row stride in bf16 elements
#define TILE_BYTES  (128 * RS * 2)     // 10240
#define AH_OFF      0
#define AL_OFF      (TILE_BYTES)
#define BH_OFF      (2 * TILE_BYTES)
#define BL_OFF      (3 * TILE_BYTES)
#define STAGE_BYTES (4 * TILE_BYTES)   // 40960
#define SMEM_REQ    (2 * STAGE_BYTES)  // 81920

// ---------------------------------------------------------------------------
// Weight transpose + bf16 hi/lo split: in [L][K][N] f32 -> out [L][N][K] bf16
// ---------------------------------------------------------------------------
template <int K, int N, int WSEL>
__global__ void transpose_split(const float* __restrict__ W) {
    __shared__ float t[32][33];
    bf16* ohi = (WSEL == 1) ? g_W1T_hi : (WSEL == 2) ? g_W2T_hi : g_W3T_hi;
    bf16* olo = (WSEL == 1) ? g_W1T_lo : (WSEL == 2) ? g_W2T_lo : g_W3T_lo;
    const int k0 = blockIdx.x * 32, n0 = blockIdx.y * 32;
    const size_t off = (size_t)blockIdx.z * K * N;
    const int tx = threadIdx.x, ty = threadIdx.y;
#pragma unroll
    for (int i = 0; i < 4; i++)
        t[ty + 8 * i][tx] = W[off + (size_t)(k0 + ty + 8 * i) * N + n0 + tx];
    __syncthreads();
#pragma unroll
    for (int i = 0; i < 4; i++) {
        float v = t[tx][ty + 8 * i];
        int n = n0 + ty + 8 * i;
        int k = k0 + tx;
        bf16 h = __float2bfloat16(v);
        bf16 l = __float2bfloat16(v - __bfloat162float(h));
        ohi[off + (size_t)n * K + k] = h;
        olo[off + (size_t)n * K + k] = l;
    }
}

// ---------------------------------------------------------------------------
// Init: x = z, logdet = 0, A0 = bf16split(z[:, im(parity=0)])
// ---------------------------------------------------------------------------
__global__ void init_kernel(const float* __restrict__ z, float* __restrict__ x,
                            float* __restrict__ logdet) {
    const int r = blockIdx.x;
    const int tid = threadIdx.x;
    const float4* zr = (const float4*)(z + (size_t)r * N_);
    float4* xr = (float4*)(x + (size_t)r * N_);
#pragma unroll
    for (int i = tid; i < N_ / 4; i += 256) xr[i] = zr[i];
    const float* zrow = z + (size_t)r * N_;
#pragma unroll
    for (int c = tid; c < NM_; c += 256) {
        float v = zrow[gather_im(c, 0)];
        bf16 h = __float2bfloat16(v);
        g_A_hi[(size_t)r * NM_ + c] = h;
        g_A_lo[(size_t)r * NM_ + c] = __float2bfloat16(v - __bfloat162float(h));
    }
    if (tid == 0) logdet[r] = 0.0f;
}

// ---------------------------------------------------------------------------
// mma.sync GEMM: D[128 x 128] = A[128 x K_TOT] * B^T  (hi/lo, 3 products)
//   ASRC: 0=g_A  1=g_h1  2=g_h2
//   BSRC: 1=W1T  2=W2T   3=W3T (split s/t column mapping)
//   MODE: 0 = bias+leaky -> bf16 hi/lo into CDST (1=g_h1, 2=g_h2)
//         1 = fused coupling update (s/t), writes x, logdet, g_A(next layer)
// 8 warps: warp grid 2(m) x 4(n); warp tile 64x32 = 4x4 m16n8k16 frags.
// ---------------------------------------------------------------------------
template <int K_TOT, int ASRC, int BSRC, int MODE, int CDST>
__global__ void __launch_bounds__(256, 1)
gemm_mma(const float* __restrict__ bias, float* __restrict__ x,
         float* __restrict__ logdet, int layer, int parity) {
    extern __shared__ __align__(16) char smem[];
    const uint32_t sba = smem_u32(smem);
    const int tid = threadIdx.x;
    const int wid = tid >> 5;
    const int lid = tid & 31;
    const int g   = lid >> 2;       // 0..7
    const int t4  = lid & 3;        // 0..3
    const int wm  = wid & 1;        // 0..1 (m)
    const int wn  = wid >> 1;       // 0..3 (n)
    const int row0 = blockIdx.y * 128;
    const int bx   = blockIdx.x;
    constexpr int NSTAGE = K_TOT / 32;

    // operand pointers
    const bf16* Ah = (ASRC == 0) ? g_A_hi : (ASRC == 1) ? g_h1_hi : g_h2_hi;
    const bf16* Al = (ASRC == 0) ? g_A_lo : (ASRC == 1) ? g_h1_lo : g_h2_lo;
    const bf16* Bh;
    const bf16* Bl;
    if (BSRC == 1) { Bh = g_W1T_hi + (size_t)layer * H_ * NM_; Bl = g_W1T_lo + (size_t)layer * H_ * NM_; }
    else if (BSRC == 2) { Bh = g_W2T_hi + (size_t)layer * H_ * H_; Bl = g_W2T_lo + (size_t)layer * H_ * H_; }
    else { Bh = g_W3T_hi + (size_t)layer * (size_t)N_ * H_; Bl = g_W3T_lo + (size_t)layer * (size_t)N_ * H_; }

    // B tile row (n in 0..127) -> global W^T row
    auto brow = [&](int n) -> int {
        if (BSRC == 3) return (n < 64) ? (bx * 64 + n) : (2048 + bx * 64 + (n - 64));
        return bx * 128 + n;
    };

    // ---- async stage loader: 8 cp.async/thread ----
    auto issue = [&](int chunk) {
        const uint32_t st = sba + (chunk & 1) * STAGE_BYTES;
        const int k0 = chunk * 32;
#pragma unroll
        for (int i = 0; i < 2; i++) {
            const int ch = tid + i * 256;      // 0..511
            const int rr = ch >> 2;            // 0..127
            const int kc = ch & 3;             // 16B chunk within 64B row
            const uint32_t so = (uint32_t)(rr * 80 + kc * 16);
            const size_t ga = (size_t)(row0 + rr) * K_TOT + k0 + kc * 8;
            CPA16(st + AH_OFF + so, Ah + ga);
            CPA16(st + AL_OFF + so, Al + ga);
            const size_t gb = (size_t)brow(rr) * K_TOT + k0 + kc * 8;
            CPA16(st + BH_OFF + so, Bh + gb);
            CPA16(st + BL_OFF + so, Bl + gb);
        }
        CP_COMMIT();
    };

    float acc[4][4][4];
#pragma unroll
    for (int i = 0; i < 4; i++)
#pragma unroll
        for (int j = 0; j < 4; j++)
#pragma unroll
            for (int q = 0; q < 4; q++) acc[i][j][q] = 0.0f;

    // ---- compute one 32-wide K stage ----
    auto compute = [&](int chunk) {
        const char* st = smem + (chunk & 1) * STAGE_BYTES;
        const char* pAH = st + AH_OFF;
        const char* pAL = st + AL_OFF;
        const char* pBH = st + BH_OFF;
        const char* pBL = st + BL_OFF;
#pragma unroll
        for (int kk = 0; kk < 32; kk += 16) {
            const int kc = kk + t4 * 2;
            uint32_t ah[4][4], bh4[4][2];
            // load A-hi frags
#pragma unroll
            for (int mt = 0; mt < 4; mt++) {
                const int r0 = wm * 64 + mt * 16 + g;
                ah[mt][0] = *(const uint32_t*)(pAH + (r0 * RS + kc) * 2);
                ah[mt][1] = *(const uint32_t*)(pAH + ((r0 + 8) * RS + kc) * 2);
                ah[mt][2] = *(const uint32_t*)(pAH + (r0 * RS + kc + 8) * 2);
                ah[mt][3] = *(const uint32_t*)(pAH + ((r0 + 8) * RS + kc + 8) * 2);
            }
            // load B-hi frags
#pragma unroll
            for (int nt = 0; nt < 4; nt++) {
                const int n0 = wn * 32 + nt * 8 + g;
                bh4[nt][0] = *(const uint32_t*)(pBH + (n0 * RS + kc) * 2);
                bh4[nt][1] = *(const uint32_t*)(pBH + (n0 * RS + kc + 8) * 2);
            }
            // pass 1: Ahi * Bhi
#pragma unroll
            for (int mt = 0; mt < 4; mt++)
#pragma unroll
                for (int nt = 0; nt < 4; nt++) mma_bf16(acc[mt][nt], ah[mt], bh4[nt]);
            // pass 2: Alo * Bhi
            {
                uint32_t al[4][4];
#pragma unroll
                for (int mt = 0; mt < 4; mt++) {
                    const int r0 = wm * 64 + mt * 16 + g;
                    al[mt][0] = *(const uint32_t*)(pAL + (r0 * RS + kc) * 2);
                    al[mt][1] = *(const uint32_t*)(pAL + ((r0 + 8) * RS + kc) * 2);
                    al[mt][2] = *(const uint32_t*)(pAL + (r0 * RS + kc + 8) * 2);
                    al[mt][3] = *(const uint32_t*)(pAL + ((r0 + 8) * RS + kc + 8) * 2);
                }
#pragma unroll
                for (int mt = 0; mt < 4; mt++)
#pragma unroll
                    for (int nt = 0; nt < 4; nt++) mma_bf16(acc[mt][nt], al[mt], bh4[nt]);
            }
            // pass 3: Ahi * Blo
            {
                uint32_t bl4[4][2];
#pragma unroll
                for (int nt = 0; nt < 4; nt++) {
                    const int n0 = wn * 32 + nt * 8 + g;
                    bl4[nt][0] = *(const uint32_t*)(pBL + (n0 * RS + kc) * 2);
                    bl4[nt][1] = *(const uint32_t*)(pBL + (n0 * RS + kc + 8) * 2);
                }
#pragma unroll
                for (int mt = 0; mt < 4; mt++)
#pragma unroll
                    for (int nt = 0; nt < 4; nt++) mma_bf16(acc[mt][nt], ah[mt], bl4[nt]);
            }
        }
    };

    // ---- pipelined main loop (2-stage cp.async) ----
    issue(0);
    for (int c = 0; c < NSTAGE; c++) {
        if (c + 1 < NSTAGE) { issue(c + 1); CP_WAIT1(); }
        else                { CP_WAIT0(); }
        __syncthreads();
        compute(c);
        __syncthreads();
    }

    // ---- epilogue ----
    if (MODE == 0) {
        bf16* Oh = (CDST == 1) ? g_h1_hi : g_h2_hi;
        bf16* Ol = (CDST == 1) ? g_h1_lo : g_h2_lo;
#pragma unroll
        for (int mt = 0; mt < 4; mt++) {
#pragma unroll
            for (int nt = 0; nt < 4; nt++) {
                const int colg = bx * 128 + wn * 32 + nt * 8 + t4 * 2;
                const float bv0 = bias[colg], bv1 = bias[colg + 1];
#pragma unroll
                for (int half = 0; half < 2; half++) {
                    const int r = row0 + wm * 64 + mt * 16 + g + half * 8;
                    float v0 = acc[mt][nt][half * 2 + 0] + bv0;
                    float v1 = acc[mt][nt][half * 2 + 1] + bv1;
                    v0 = v0 > 0.f ? v0 : 0.2f * v0;
                    v1 = v1 > 0.f ? v1 : 0.2f * v1;
                    bf16 h0 = __float2bfloat16(v0);
                    bf16 h1 = __float2bfloat16(v1);
                    __nv_bfloat162 hh; hh.x = h0; hh.y = h1;
                    __nv_bfloat162 ll;
                    ll.x = __float2bfloat16(v0 - __bfloat162float(h0));
                    ll.y = __float2bfloat16(v1 - __bfloat162float(h1));
                    *(__nv_bfloat162*)(&Oh[(size_t)r * H_ + colg]) = hh;
                    *(__nv_bfloat162*)(&Ol[(size_t)r * H_ + colg]) = ll;
                }
            }
        }
    } else {
        // stage raw accumulators to smem: cols 0..63 = s-pre, 64..127 = t-pre
        float* sb = (float*)smem;                        // [128][130]
        float* rowsum = (float*)(smem + 128 * 130 * 4);  // [128]
#pragma unroll
        for (int mt = 0; mt < 4; mt++)
#pragma unroll
            for (int nt = 0; nt < 4; nt++) {
                const int cl = wn * 32 + nt * 8 + t4 * 2;
#pragma unroll
                for (int half = 0; half < 2; half++) {
                    const int rl = wm * 64 + mt * 16 + g + half * 8;
                    sb[rl * 130 + cl]     = acc[mt][nt][half * 2 + 0];
                    sb[rl * 130 + cl + 1] = acc[mt][nt][half * 2 + 1];
                }
            }
        if (tid < 128) rowsum[tid] = 0.0f;
        __syncthreads();

        // coupling update: 128 rows x 64 cols, 32 elems/thread
#pragma unroll 4
        for (int i = tid; i < 128 * 64; i += 256) {
            const int rl = i >> 6;
            const int c  = i & 63;
            const int cs = bx * 64 + c;
            const float sp = sb[rl * 130 + c] + bias[cs];
            const float s  = 2.0f * tanhf(sp);
            const float tv = sb[rl * 130 + 64 + c] + bias[2048 + cs];
            const int r = row0 + rl;
            float* xrow = x + (size_t)r * N_;
            const int jcol = gather_iu(cs, parity);
            const float nv = xrow[jcol] * __expf(s) + tv;
            xrow[jcol] = nv;
            atomicAdd(&rowsum[rl], s);
            bf16 h = __float2bfloat16(nv);
            g_A_hi[(size_t)r * NM_ + cs] = h;
            g_A_lo[(size_t)r * NM_ + cs] = __float2bfloat16(nv - __bfloat162float(h));
        }
        __syncthreads();
        if (tid < 128) atomicAdd(&logdet[row0 + tid], rowsum[tid]);
    }
}

// ---------------------------------------------------------------------------
// Launch
// ---------------------------------------------------------------------------
extern "C" void kernel_launch(void* const* d_in, const int* in_sizes, int n_in,
                              void* d_out, int out_size) {
    const float* z  = (const float*)d_in[0];
    const float* W1 = (const float*)d_in[1];
    const float* b1 = (const float*)d_in[2];
    const float* W2 = (const float*)d_in[3];
    const float* b2 = (const float*)d_in[4];
    const float* W3 = (const float*)d_in[5];
    const float* b3 = (const float*)d_in[6];

    float* x      = (float*)d_out;
    float* logdet = x + (size_t)B_ * N_;

    cudaFuncSetAttribute(gemm_mma<2048, 0, 1, 0, 1>, cudaFuncAttributeMaxDynamicSharedMemorySize, SMEM_REQ);
    cudaFuncSetAttribute(gemm_mma<256, 1, 2, 0, 2>,  cudaFuncAttributeMaxDynamicSharedMemorySize, SMEM_REQ);
    cudaFuncSetAttribute(gemm_mma<256, 2, 3, 1, 0>,  cudaFuncAttributeMaxDynamicSharedMemorySize, SMEM_REQ);

    // weight prep (transpose + hi/lo split)
    transpose_split<NM_, H_, 1><<<dim3(NM_ / 32, H_ / 32, NLAY_), dim3(32, 8)>>>(W1);
    transpose_split<H_, H_, 2><<<dim3(H_ / 32, H_ / 32, NLAY_), dim3(32, 8)>>>(W2);
    transpose_split<H_, N_, 3><<<dim3(H_ / 32, N_ / 32, NLAY_), dim3(32, 8)>>>(W3);

    init_kernel<<<B_, 256>>>(z, x, logdet);

    for (int l = 0; l < NLAY_; l++) {
        const int p = l & 1;
        // h1 = leaky( A @ W1^T + b1 )
        gemm_mma<2048, 0, 1, 0, 1><<<dim3(2, B_ / 128), 256, SMEM_REQ>>>(b1 + (size_t)l * H_, x, logdet, l, p);
        // h2 = leaky( h1 @ W2^T + b2 )
        gemm_mma<256, 1, 2, 0, 2><<<dim3(2, B_ / 128), 256, SMEM_REQ>>>(b2 + (size_t)l * H_, x, logdet, l, p);
        // fused: st = h2 @ W3^T + b3 ; coupling update
        gemm_mma<256, 2, 3, 1, 0><<<dim3(32, B_ / 128), 256, SMEM_REQ>>>(b3 + (size_t)l * N_, x, logdet, l, p);
    }
}

// round 5
// speedup vs baseline: 2.2476x; 2.2476x over previous
#include <cuda_runtime.h>
#include <cstdint>
#include <math.h>

#define B_   8192
#define N_   4096
#define H_   256
#define NM_  2048
#define NLAY_ 8

typedef unsigned long long u64;

// ---------------------------------------------------------------------------
// Scratch (static device globals — no allocation)
// ---------------------------------------------------------------------------
__device__ __align__(256) float g_A [(size_t)B_ * NM_];   // 64 MB  masked half (dense, fp32)
__device__ __align__(256) float g_h1[(size_t)B_ * H_];    //  8 MB
__device__ __align__(256) float g_h2[(size_t)B_ * H_];    //  8 MB

// ---------------------------------------------------------------------------
// Helpers
// ---------------------------------------------------------------------------
__device__ __forceinline__ uint32_t smem_u32(const void* p) {
    uint32_t a;
    asm("{ .reg .u64 t; cvta.to.shared.u64 t, %1; cvt.u32.u64 %0, t; }" : "=r"(a) : "l"(p));
    return a;
}

#define CPA16(sm, gp) \
    asm volatile("cp.async.cg.shared.global [%0], [%1], 16;" :: "r"(sm), "l"(gp) : "memory")
#define CP_COMMIT() asm volatile("cp.async.commit_group;" ::: "memory")
#define CP_WAIT0()  asm volatile("cp.async.wait_group 0;" ::: "memory")

// packed fp32x2 FMA: d = a*b + d   (both halves)
__device__ __forceinline__ void fma2(u64& d, u64 a, u64 b) {
    asm("fma.rn.f32x2 %0, %1, %2, %0;" : "+l"(d) : "l"(a), "l"(b));
}
__device__ __forceinline__ float2 u2f(u64 v) {
    float2 f;
    f.x = __uint_as_float((unsigned)v);
    f.y = __uint_as_float((unsigned)(v >> 32));
    return f;
}
__device__ __forceinline__ u64 dupf(float v) {
    u64 b = (u64)__float_as_uint(v);
    return b | (b << 32);
}

// checkerboard index math (see round-2 derivation)
__device__ __forceinline__ int gather_im(int c, int p) {
    int g = c >> 5, m = c & 31;
    return g * 64 + 2 * m + ((p + g) & 1);
}
__device__ __forceinline__ int gather_iu(int c, int p) {
    int g = c >> 5, m = c & 31;
    return g * 64 + 2 * m + ((p + g + 1) & 1);
}

// ---------------------------------------------------------------------------
// Init: x = z, logdet = 0, g_A = z[:, im(parity=0)]
// ---------------------------------------------------------------------------
__global__ void init_kernel(const float* __restrict__ z, float* __restrict__ x,
                            float* __restrict__ logdet) {
    const int r = blockIdx.x;
    const int tid = threadIdx.x;
    const float4* zr = (const float4*)(z + (size_t)r * N_);
    float4* xr = (float4*)(x + (size_t)r * N_);
#pragma unroll
    for (int i = tid; i < N_ / 4; i += 256) xr[i] = zr[i];
    const float* zrow = z + (size_t)r * N_;
#pragma unroll
    for (int c = tid; c < NM_; c += 256) g_A[(size_t)r * NM_ + c] = zrow[gather_im(c, 0)];
    if (tid == 0) logdet[r] = 0.0f;
}

// ---------------------------------------------------------------------------
// f32x2 SGEMM:  D[128 x 128] = A[128 x K_TOT] @ W-slice  (+bias, +act / +fused update)
//   ASRC: 0=g_A  1=g_h1  2=g_h2       W used in native [K][ldw] layout.
//   MODE 0: leaky + store fp32 to CDST (1=g_h1, 2=g_h2); cols = bx*128 ..
//   MODE 1: B cols = {bx*64..+63} (s)  U  {2048+bx*64..+63} (t); fused coupling
//           update of x + logdet + write next-layer g_A.
// 256 threads; thread tile = 8 rows x (4 cols @nOff + 4 cols @nOff+64).
// A duplicated in smem as {a,a} u64 pairs -> inner loop is pure LDS.128 + fma.f32x2.
// ---------------------------------------------------------------------------
template <int K_TOT, int ASRC, int MODE, int CDST>
__global__ void __launch_bounds__(256, 2)
gemm_f32x2(const float* __restrict__ W, int ldw,
           const float* __restrict__ bias, float* __restrict__ x,
           float* __restrict__ logdet, int parity) {
    __shared__ u64   As2[16][128];        // 16 KB (k-major, dup pairs)
    __shared__ float Bs[2][16][128];      // 2 x 8 KB

    const int tid  = threadIdx.x;
    const int row0 = blockIdx.y * 128;
    const int bx   = blockIdx.x;
    const int tRow = (tid >> 4) * 8;      // 0..120
    const int nOff = (tid & 15) * 4;      // 0..60
    constexpr int NS = K_TOT / 16;

    // A loader indices: ch = tid + 256*i -> row = ch>>2, kq = ch&3 (float4 each)
    const int aRow = tid >> 2;
    const int aKq  = tid & 3;

    const float* Aptr = (ASRC == 0) ? g_A : (ASRC == 1) ? g_h1 : g_h2;
    Aptr += (size_t)row0 * K_TOT;

    // ---- B cp.async loader ----
    const uint32_t bsBase = smem_u32(&Bs[0][0][0]);
    auto loadB = [&](int kt, int buf) {
#pragma unroll
        for (int i = 0; i < 2; i++) {
            const int ch = tid + i * 256;          // 0..511
            const int k  = ch >> 5;                // 0..15
            int col;
            if (MODE == 1) {
                const int seg = (ch >> 4) & 1;
                const int c   = ch & 15;
                col = (seg ? 2048 + bx * 64 : bx * 64) + c * 4;
                const uint32_t so = bsBase + buf * 8192 + (k * 128 + seg * 64 + c * 4) * 4;
                CPA16(so, W + (size_t)(kt + k) * ldw + col);
            } else {
                const int c = ch & 31;
                col = bx * 128 + c * 4;
                const uint32_t so = bsBase + buf * 8192 + (k * 128 + c * 4) * 4;
                CPA16(so, W + (size_t)(kt + k) * ldw + col);
            }
        }
        CP_COMMIT();
    };

    auto loadA = [&](int kt, float4* ar) {
#pragma unroll
        for (int i = 0; i < 2; i++) {
            const int row = aRow + i * 64;
            ar[i] = *(const float4*)(Aptr + (size_t)row * K_TOT + kt + aKq * 4);
        }
    };
    auto storeA = [&](const float4* ar) {
#pragma unroll
        for (int i = 0; i < 2; i++) {
            const int row = aRow + i * 64;
            As2[aKq * 4 + 0][row] = dupf(ar[i].x);
            As2[aKq * 4 + 1][row] = dupf(ar[i].y);
            As2[aKq * 4 + 2][row] = dupf(ar[i].z);
            As2[aKq * 4 + 3][row] = dupf(ar[i].w);
        }
    };

    u64 acc[8][4];
#pragma unroll
    for (int i = 0; i < 8; i++)
#pragma unroll
        for (int j = 0; j < 4; j++) acc[i][j] = 0ULL;

    // ---- prologue: stage 0 ----
    {
        float4 ar[2];
        loadA(0, ar);
        storeA(ar);
        loadB(0, 0);
        CP_WAIT0();
        __syncthreads();
    }

    // ---- main loop ----
    for (int c = 0; c < NS; c++) {
        float4 ar[2];
        if (c + 1 < NS) {
            loadA((c + 1) * 16, ar);
            loadB((c + 1) * 16, (c + 1) & 1);
        }
        // compute stage c
        {
            const int buf = c & 1;
#pragma unroll
            for (int k = 0; k < 16; k++) {
                u64 a[8];
#pragma unroll
                for (int i = 0; i < 4; i++) {
                    ulonglong2 av = *(const ulonglong2*)&As2[k][tRow + 2 * i];
                    a[2 * i]     = av.x;
                    a[2 * i + 1] = av.y;
                }
                const ulonglong2 b0 = *(const ulonglong2*)&Bs[buf][k][nOff];
                const ulonglong2 b1 = *(const ulonglong2*)&Bs[buf][k][nOff + 64];
#pragma unroll
                for (int i = 0; i < 8; i++) {
                    fma2(acc[i][0], a[i], b0.x);
                    fma2(acc[i][1], a[i], b0.y);
                    fma2(acc[i][2], a[i], b1.x);
                    fma2(acc[i][3], a[i], b1.y);
                }
            }
        }
        __syncthreads();
        if (c + 1 < NS) {
            storeA(ar);
            CP_WAIT0();
        }
        __syncthreads();
    }

    // ---- epilogue ----
    if (MODE == 0) {
        float* Out = (CDST == 1) ? g_h1 : g_h2;
        const int c0 = bx * 128 + nOff;
        const int c1 = c0 + 64;
        const float bl0 = bias[c0], bl1 = bias[c0 + 1], bl2 = bias[c0 + 2], bl3 = bias[c0 + 3];
        const float bh0 = bias[c1], bh1 = bias[c1 + 1], bh2 = bias[c1 + 2], bh3 = bias[c1 + 3];
#pragma unroll
        for (int i = 0; i < 8; i++) {
            const int r = row0 + tRow + i;
            float2 p0 = u2f(acc[i][0]), p1 = u2f(acc[i][1]);
            float2 p2 = u2f(acc[i][2]), p3 = u2f(acc[i][3]);
            float4 v0, v1;
            v0.x = p0.x + bl0; v0.y = p0.y + bl1; v0.z = p1.x + bl2; v0.w = p1.y + bl3;
            v1.x = p2.x + bh0; v1.y = p2.y + bh1; v1.z = p3.x + bh2; v1.w = p3.y + bh3;
            v0.x = v0.x > 0.f ? v0.x : 0.2f * v0.x;
            v0.y = v0.y > 0.f ? v0.y : 0.2f * v0.y;
            v0.z = v0.z > 0.f ? v0.z : 0.2f * v0.z;
            v0.w = v0.w > 0.f ? v0.w : 0.2f * v0.w;
            v1.x = v1.x > 0.f ? v1.x : 0.2f * v1.x;
            v1.y = v1.y > 0.f ? v1.y : 0.2f * v1.y;
            v1.z = v1.z > 0.f ? v1.z : 0.2f * v1.z;
            v1.w = v1.w > 0.f ? v1.w : 0.2f * v1.w;
            *(float4*)(Out + (size_t)r * H_ + c0) = v0;
            *(float4*)(Out + (size_t)r * H_ + c1) = v1;
        }
    } else {
        // acc[i][0..1] = s-pre for cols cs0..cs0+3 ; acc[i][2..3] = t-pre (same cols)
        const int cs0 = bx * 64 + nOff;
        const float bs0 = bias[cs0], bs1 = bias[cs0 + 1], bs2 = bias[cs0 + 2], bs3 = bias[cs0 + 3];
        const float bt0 = bias[2048 + cs0], bt1 = bias[2048 + cs0 + 1];
        const float bt2 = bias[2048 + cs0 + 2], bt3 = bias[2048 + cs0 + 3];
        const int j0 = gather_iu(cs0, parity);
        const int j1 = gather_iu(cs0 + 1, parity);
        const int j2 = gather_iu(cs0 + 2, parity);
        const int j3 = gather_iu(cs0 + 3, parity);
#pragma unroll
        for (int i = 0; i < 8; i++) {
            const int r = row0 + tRow + i;
            float* xrow = x + (size_t)r * N_;
            float* arow = g_A + (size_t)r * NM_;
            float2 s01 = u2f(acc[i][0]), s23 = u2f(acc[i][1]);
            float2 t01 = u2f(acc[i][2]), t23 = u2f(acc[i][3]);
            float sp[4] = { s01.x + bs0, s01.y + bs1, s23.x + bs2, s23.y + bs3 };
            float tp[4] = { t01.x + bt0, t01.y + bt1, t23.x + bt2, t23.y + bt3 };
            const int jc[4] = { j0, j1, j2, j3 };
            float ssum = 0.0f;
#pragma unroll
            for (int q = 0; q < 4; q++) {
                // s = 2*tanh(sp) via exp: tanh(u) = 1 - 2/(e^{2u}+1)
                const float e2u = __expf(2.0f * sp[q]);
                const float s   = 2.0f - 4.0f / (e2u + 1.0f);
                const float nv  = xrow[jc[q]] * __expf(s) + tp[q];
                xrow[jc[q]] = nv;
                arow[cs0 + q] = nv;
                ssum += s;
            }
            // reduce ssum across the 16 threads sharing this row (half-warp)
            ssum += __shfl_xor_sync(0xffffffffu, ssum, 1);
            ssum += __shfl_xor_sync(0xffffffffu, ssum, 2);
            ssum += __shfl_xor_sync(0xffffffffu, ssum, 4);
            ssum += __shfl_xor_sync(0xffffffffu, ssum, 8);
            if ((tid & 15) == 0) atomicAdd(&logdet[r], ssum);
        }
    }
}

// ---------------------------------------------------------------------------
// Launch
// ---------------------------------------------------------------------------
extern "C" void kernel_launch(void* const* d_in, const int* in_sizes, int n_in,
                              void* d_out, int out_size) {
    const float* z  = (const float*)d_in[0];
    const float* W1 = (const float*)d_in[1];
    const float* b1 = (const float*)d_in[2];
    const float* W2 = (const float*)d_in[3];
    const float* b2 = (const float*)d_in[4];
    const float* W3 = (const float*)d_in[5];
    const float* b3 = (const float*)d_in[6];

    float* x      = (float*)d_out;
    float* logdet = x + (size_t)B_ * N_;

    init_kernel<<<B_, 256>>>(z, x, logdet);

    for (int l = 0; l < NLAY_; l++) {
        const int p = l & 1;
        const float* w1 = W1 + (size_t)l * NM_ * H_;
        const float* w2 = W2 + (size_t)l * H_ * H_;
        const float* w3 = W3 + (size_t)l * H_ * N_;

        // h1 = leaky( A @ W1 + b1 )        (8192x2048)(2048x256)
        gemm_f32x2<NM_, 0, 0, 1><<<dim3(2, B_ / 128), 256>>>(w1, H_, b1 + (size_t)l * H_, x, logdet, p);
        // h2 = leaky( h1 @ W2 + b2 )       (8192x256)(256x256)
        gemm_f32x2<H_, 1, 0, 2><<<dim3(2, B_ / 128), 256>>>(w2, H_, b2 + (size_t)l * H_, x, logdet, p);
        // fused: st = h2 @ W3 + b3 ; coupling update + next-layer A
        gemm_f32x2<H_, 2, 1, 0><<<dim3(32, B_ / 128), 256>>>(w3, N_, b3 + (size_t)l * N_, x, logdet, p);
    }
}

// round 6
// speedup vs baseline: 2.3631x; 1.0514x over previous
#include <cuda_runtime.h>
#include <cstdint>
#include <math.h>

#define B_   8192
#define N_   4096
#define H_   256
#define NM_  2048
#define NLAY_ 8

typedef unsigned long long u64;

// ---------------------------------------------------------------------------
// Scratch (static device globals — no allocation)
// ---------------------------------------------------------------------------
__device__ __align__(256) float g_A [(size_t)B_ * NM_];   // 64 MB  masked half (dense fp32)
__device__ __align__(256) float g_h1[(size_t)B_ * H_];    //  8 MB
__device__ __align__(256) float g_h2[(size_t)B_ * H_];    //  8 MB

// ---------------------------------------------------------------------------
// Helpers
// ---------------------------------------------------------------------------
__device__ __forceinline__ uint32_t smem_u32(const void* p) {
    uint32_t a;
    asm("{ .reg .u64 t; cvta.to.shared.u64 t, %1; cvt.u32.u64 %0, t; }" : "=r"(a) : "l"(p));
    return a;
}

#define CPA16(sm, gp) \
    asm volatile("cp.async.cg.shared.global [%0], [%1], 16;" :: "r"(sm), "l"(gp) : "memory")
#define CP_COMMIT() asm volatile("cp.async.commit_group;" ::: "memory")
#define CP_WAIT0()  asm volatile("cp.async.wait_group 0;" ::: "memory")

// packed fp32x2 FMA: d = a*b + d (both halves)
__device__ __forceinline__ void fma2(u64& d, u64 a, u64 b) {
    asm("fma.rn.f32x2 %0, %1, %2, %0;" : "+l"(d) : "l"(a), "l"(b));
}
__device__ __forceinline__ float2 u2f(u64 v) {
    float2 f;
    f.x = __uint_as_float((unsigned)v);
    f.y = __uint_as_float((unsigned)(v >> 32));
    return f;
}
__device__ __forceinline__ u64 dupf(float v) {
    u64 b = (u64)__float_as_uint(v);
    return b | (b << 32);
}

// checkerboard index math
__device__ __forceinline__ int gather_im(int c, int p) {
    int g = c >> 5, m = c & 31;
    return g * 64 + 2 * m + ((p + g) & 1);
}
__device__ __forceinline__ int gather_iu(int c, int p) {
    int g = c >> 5, m = c & 31;
    return g * 64 + 2 * m + ((p + g + 1) & 1);
}

// ---------------------------------------------------------------------------
// Init: x = z, logdet = 0, g_A = z[:, im(parity=0)]
// ---------------------------------------------------------------------------
__global__ void init_kernel(const float* __restrict__ z, float* __restrict__ x,
                            float* __restrict__ logdet) {
    const int r = blockIdx.x;
    const int tid = threadIdx.x;
    const float4* zr = (const float4*)(z + (size_t)r * N_);
    float4* xr = (float4*)(x + (size_t)r * N_);
#pragma unroll
    for (int i = tid; i < N_ / 4; i += 256) xr[i] = zr[i];
    const float* zrow = z + (size_t)r * N_;
#pragma unroll
    for (int c = tid; c < NM_; c += 256) g_A[(size_t)r * NM_ + c] = zrow[gather_im(c, 0)];
    if (tid == 0) logdet[r] = 0.0f;
}

// ---------------------------------------------------------------------------
// f32x2 SGEMM:  D[64 x 128] = A[64 x K_TOT] @ W-slice (+bias+act / fused update)
//   CTA: 128 threads, 4 CTAs/SM. Thread tile 8 rows x (4 + 4) cols.
//   Double-buffered A (dup-pair u64) and B smem; ONE __syncthreads per stage.
//   ASRC: 0=g_A 1=g_h1 2=g_h2.  W native [K][ldw].
//   MODE 0: leaky -> CDST (1=g_h1, 2=g_h2), cols bx*128..
//   MODE 1: cols {bx*64(s)} U {2048+bx*64(t)}; fused coupling update.
// ---------------------------------------------------------------------------
template <int K_TOT, int ASRC, int MODE, int CDST>
__global__ void __launch_bounds__(128, 4)
gemm_f32x2(const float* __restrict__ W, int ldw,
           const float* __restrict__ bias, float* __restrict__ x,
           float* __restrict__ logdet, int parity) {
    __shared__ u64   As2[2][16][64];      // 16 KB total (k-major, dup pairs)
    __shared__ float Bs[2][16][128];      // 16 KB total

    const int tid  = threadIdx.x;
    const int row0 = blockIdx.y * 64;
    const int bx   = blockIdx.x;
    const int tRow = (tid >> 4) * 8;      // 0..56
    const int nOff = (tid & 15) * 4;      // 0..60
    constexpr int NS = K_TOT / 16;

    // A loader: 256 float4-chunks (64 rows x 4 kq) over 128 threads, 2 each
    const int aRow = tid >> 1;            // 0..63
    const int aKq  = tid & 1;             // chunk pair base: loads kq = aKq*2, aKq*2+1? no:
    // simpler: ch = tid + 128*i -> row = ch>>2 (0..63), kq = ch&3
    const float* Aptr = (ASRC == 0) ? g_A : (ASRC == 1) ? g_h1 : g_h2;
    Aptr += (size_t)row0 * K_TOT;

    const uint32_t bsBase = smem_u32(&Bs[0][0][0]);

    auto loadB = [&](int kt, int buf) {
#pragma unroll
        for (int i = 0; i < 4; i++) {
            const int ch = tid + i * 128;          // 0..511
            const int k  = ch >> 5;                // 0..15
            if (MODE == 1) {
                const int seg = (ch >> 4) & 1;
                const int c   = ch & 15;
                const int col = (seg ? 2048 + bx * 64 : bx * 64) + c * 4;
                const uint32_t so = bsBase + buf * 8192 + (k * 128 + seg * 64 + c * 4) * 4;
                CPA16(so, W + (size_t)(kt + k) * ldw + col);
            } else {
                const int c = ch & 31;
                const int col = bx * 128 + c * 4;
                const uint32_t so = bsBase + buf * 8192 + (k * 128 + c * 4) * 4;
                CPA16(so, W + (size_t)(kt + k) * ldw + col);
            }
        }
        CP_COMMIT();
    };

    auto loadA = [&](int kt, float4* ar) {
#pragma unroll
        for (int i = 0; i < 2; i++) {
            const int ch = tid + i * 128;
            const int row = ch >> 2, kq = ch & 3;
            ar[i] = *(const float4*)(Aptr + (size_t)row * K_TOT + kt + kq * 4);
        }
    };
    auto storeA = [&](const float4* ar, int buf) {
#pragma unroll
        for (int i = 0; i < 2; i++) {
            const int ch = tid + i * 128;
            const int row = ch >> 2, kq = ch & 3;
            As2[buf][kq * 4 + 0][row] = dupf(ar[i].x);
            As2[buf][kq * 4 + 1][row] = dupf(ar[i].y);
            As2[buf][kq * 4 + 2][row] = dupf(ar[i].z);
            As2[buf][kq * 4 + 3][row] = dupf(ar[i].w);
        }
    };

    u64 acc[8][4];
#pragma unroll
    for (int i = 0; i < 8; i++)
#pragma unroll
        for (int j = 0; j < 4; j++) acc[i][j] = 0ULL;

    // ---- prologue ----
    {
        float4 ar[2];
        loadB(0, 0);
        loadA(0, ar);
        storeA(ar, 0);
        CP_WAIT0();
        __syncthreads();
    }

    // ---- main loop: one barrier per stage ----
    for (int c = 0; c < NS; c++) {
        float4 ar[2];
        const int nb = (c + 1) & 1;
        if (c + 1 < NS) {
            loadA((c + 1) * 16, ar);
            loadB((c + 1) * 16, nb);
        }
        {
            const int buf = c & 1;
#pragma unroll
            for (int k = 0; k < 16; k++) {
                u64 a[8];
#pragma unroll
                for (int i = 0; i < 4; i++) {
                    ulonglong2 av = *(const ulonglong2*)&As2[buf][k][tRow + 2 * i];
                    a[2 * i]     = av.x;
                    a[2 * i + 1] = av.y;
                }
                const ulonglong2 b0 = *(const ulonglong2*)&Bs[buf][k][nOff];
                const ulonglong2 b1 = *(const ulonglong2*)&Bs[buf][k][nOff + 64];
#pragma unroll
                for (int i = 0; i < 8; i++) {
                    fma2(acc[i][0], a[i], b0.x);
                    fma2(acc[i][1], a[i], b0.y);
                    fma2(acc[i][2], a[i], b1.x);
                    fma2(acc[i][3], a[i], b1.y);
                }
            }
        }
        if (c + 1 < NS) {
            storeA(ar, nb);
            CP_WAIT0();
        }
        __syncthreads();
    }

    // ---- epilogue ----
    if (MODE == 0) {
        float* Out = (CDST == 1) ? g_h1 : g_h2;
        const int c0 = bx * 128 + nOff;
        const int c1 = c0 + 64;
        const float bl0 = bias[c0], bl1 = bias[c0 + 1], bl2 = bias[c0 + 2], bl3 = bias[c0 + 3];
        const float bh0 = bias[c1], bh1 = bias[c1 + 1], bh2 = bias[c1 + 2], bh3 = bias[c1 + 3];
#pragma unroll
        for (int i = 0; i < 8; i++) {
            const int r = row0 + tRow + i;
            float2 p0 = u2f(acc[i][0]), p1 = u2f(acc[i][1]);
            float2 p2 = u2f(acc[i][2]), p3 = u2f(acc[i][3]);
            float4 v0, v1;
            v0.x = p0.x + bl0; v0.y = p0.y + bl1; v0.z = p1.x + bl2; v0.w = p1.y + bl3;
            v1.x = p2.x + bh0; v1.y = p2.y + bh1; v1.z = p3.x + bh2; v1.w = p3.y + bh3;
            v0.x = v0.x > 0.f ? v0.x : 0.2f * v0.x;
            v0.y = v0.y > 0.f ? v0.y : 0.2f * v0.y;
            v0.z = v0.z > 0.f ? v0.z : 0.2f * v0.z;
            v0.w = v0.w > 0.f ? v0.w : 0.2f * v0.w;
            v1.x = v1.x > 0.f ? v1.x : 0.2f * v1.x;
            v1.y = v1.y > 0.f ? v1.y : 0.2f * v1.y;
            v1.z = v1.z > 0.f ? v1.z : 0.2f * v1.z;
            v1.w = v1.w > 0.f ? v1.w : 0.2f * v1.w;
            *(float4*)(Out + (size_t)r * H_ + c0) = v0;
            *(float4*)(Out + (size_t)r * H_ + c1) = v1;
        }
    } else {
        const int cs0 = bx * 64 + nOff;
        const float bs0 = bias[cs0], bs1 = bias[cs0 + 1], bs2 = bias[cs0 + 2], bs3 = bias[cs0 + 3];
        const float bt0 = bias[2048 + cs0], bt1 = bias[2048 + cs0 + 1];
        const float bt2 = bias[2048 + cs0 + 2], bt3 = bias[2048 + cs0 + 3];
        const int j0 = gather_iu(cs0, parity);
        const int j1 = gather_iu(cs0 + 1, parity);
        const int j2 = gather_iu(cs0 + 2, parity);
        const int j3 = gather_iu(cs0 + 3, parity);
#pragma unroll
        for (int i = 0; i < 8; i++) {
            const int r = row0 + tRow + i;
            float* xrow = x + (size_t)r * N_;
            float* arow = g_A + (size_t)r * NM_;
            float2 s01 = u2f(acc[i][0]), s23 = u2f(acc[i][1]);
            float2 t01 = u2f(acc[i][2]), t23 = u2f(acc[i][3]);
            float sp[4] = { s01.x + bs0, s01.y + bs1, s23.x + bs2, s23.y + bs3 };
            float tp[4] = { t01.x + bt0, t01.y + bt1, t23.x + bt2, t23.y + bt3 };
            const int jc[4] = { j0, j1, j2, j3 };
            float ssum = 0.0f;
#pragma unroll
            for (int q = 0; q < 4; q++) {
                const float e2u = __expf(2.0f * sp[q]);       // tanh via exp
                const float s   = 2.0f - 4.0f / (e2u + 1.0f); // 2*tanh(sp)
                const float nv  = xrow[jc[q]] * __expf(s) + tp[q];
                xrow[jc[q]] = nv;
                arow[cs0 + q] = nv;
                ssum += s;
            }
            ssum += __shfl_xor_sync(0xffffffffu, ssum, 1);
            ssum += __shfl_xor_sync(0xffffffffu, ssum, 2);
            ssum += __shfl_xor_sync(0xffffffffu, ssum, 4);
            ssum += __shfl_xor_sync(0xffffffffu, ssum, 8);
            if ((tid & 15) == 0) atomicAdd(&logdet[r], ssum);
        }
    }
}

// ---------------------------------------------------------------------------
// Launch
// ---------------------------------------------------------------------------
extern "C" void kernel_launch(void* const* d_in, const int* in_sizes, int n_in,
                              void* d_out, int out_size) {
    const float* z  = (const float*)d_in[0];
    const float* W1 = (const float*)d_in[1];
    const float* b1 = (const float*)d_in[2];
    const float* W2 = (const float*)d_in[3];
    const float* b2 = (const float*)d_in[4];
    const float* W3 = (const float*)d_in[5];
    const float* b3 = (const float*)d_in[6];

    float* x      = (float*)d_out;
    float* logdet = x + (size_t)B_ * N_;

    init_kernel<<<B_, 256>>>(z, x, logdet);

    for (int l = 0; l < NLAY_; l++) {
        const int p = l & 1;
        const float* w1 = W1 + (size_t)l * NM_ * H_;
        const float* w2 = W2 + (size_t)l * H_ * H_;
        const float* w3 = W3 + (size_t)l * H_ * N_;

        // h1 = leaky( A @ W1 + b1 )      (8192x2048)(2048x256): 256 CTAs
        gemm_f32x2<NM_, 0, 0, 1><<<dim3(2, B_ / 64), 128>>>(w1, H_, b1 + (size_t)l * H_, x, logdet, p);
        // h2 = leaky( h1 @ W2 + b2 )     (8192x256)(256x256): 256 CTAs
        gemm_f32x2<H_, 1, 0, 2><<<dim3(2, B_ / 64), 128>>>(w2, H_, b2 + (size_t)l * H_, x, logdet, p);
        // fused: st = h2 @ W3 + b3 ; coupling update + next-layer A: 4096 CTAs
        gemm_f32x2<H_, 2, 1, 0><<<dim3(32, B_ / 64), 128>>>(w3, N_, b3 + (size_t)l * N_, x, logdet, p);
    }
}